// round 2
// baseline (speedup 1.0000x reference)
#include <cuda_runtime.h>
#include <math.h>

// Problem constants
#define Tt   2048      // B*S tokens
#define Dm   1024      // model dim
#define NHh  16        // heads
#define HDd  64        // head dim
#define Ll   2         // layers
#define HIDh 2048      // MoE hidden
#define Ee   8         // experts
#define Ss   1024      // seq len
#define Vv   32000     // vocab

// ---------------- scratch (device globals: allocation-free) ----------------
__device__ float g_x[Tt * Dm];
__device__ float g_xn[Tt * Dm];
__device__ float g_q[Tt * Dm];
__device__ float g_k[Tt * Dm];
__device__ float g_v[Tt * Dm];
__device__ float g_ctx[Tt * Dm];
__device__ float g_gbuf[Tt * HIDh];
__device__ int   g_cnt[Ee];
__device__ int   g_toks[Ee * Tt];
__device__ float g_wgts[Ee * Tt];

// ---------------- embedding gather ----------------
__global__ void embed_kernel(const int* __restrict__ tokens,
                             const float* __restrict__ embed,
                             float* __restrict__ x) {
    int t = blockIdx.x;
    int tok = tokens[t];
    const float4* src = (const float4*)(embed + (size_t)tok * Dm);
    float4* dst = (float4*)(x + (size_t)t * Dm);
    for (int i = threadIdx.x; i < Dm / 4; i += blockDim.x) dst[i] = src[i];
}

// ---------------- rmsnorm ----------------
__global__ void rmsnorm_kernel(const float* __restrict__ x,
                               const float* __restrict__ w,
                               float* __restrict__ y) {
    int t = blockIdx.x;
    const float* xr = x + (size_t)t * Dm;
    float s = 0.f;
    for (int i = threadIdx.x; i < Dm; i += 256) { float v = xr[i]; s += v * v; }
    __shared__ float red[256];
    red[threadIdx.x] = s;
    __syncthreads();
    for (int off = 128; off > 0; off >>= 1) {
        if (threadIdx.x < off) red[threadIdx.x] += red[threadIdx.x + off];
        __syncthreads();
    }
    float scale = rsqrtf(red[0] / (float)Dm + 1e-6f);
    for (int i = threadIdx.x; i < Dm; i += 256)
        y[(size_t)t * Dm + i] = xr[i] * scale * w[i];
}

// ---------------- generic SGEMM: C[M,N] = A[M,K] @ B[K,N] (+res) ----------------
// BM=BN=64, BK=16, 16x16 threads, 4x4 per thread. M,N multiples of 64.
__global__ void sgemm_nn(const float* __restrict__ A, const float* __restrict__ B,
                         float* C, const float* res,
                         int M, int N, int K) {
    __shared__ float As[16][64];
    __shared__ float Bs[16][64];
    int row0 = blockIdx.y * 64, col0 = blockIdx.x * 64;
    int tx = threadIdx.x, ty = threadIdx.y;
    int tid = ty * 16 + tx;
    int am = tid >> 2, ak = (tid & 3) * 4;
    int bk = tid >> 4, bn = (tid & 15) * 4;
    float acc[4][4] = {};
    for (int k0 = 0; k0 < K; k0 += 16) {
        float4 a4 = *(const float4*)(A + (size_t)(row0 + am) * K + k0 + ak);
        As[ak + 0][am] = a4.x; As[ak + 1][am] = a4.y;
        As[ak + 2][am] = a4.z; As[ak + 3][am] = a4.w;
        *(float4*)&Bs[bk][bn] = *(const float4*)(B + (size_t)(k0 + bk) * N + col0 + bn);
        __syncthreads();
#pragma unroll
        for (int kk = 0; kk < 16; kk++) {
            float a[4], b[4];
            *(float4*)a = *(float4*)&As[kk][ty * 4];
            *(float4*)b = *(float4*)&Bs[kk][tx * 4];
#pragma unroll
            for (int i = 0; i < 4; i++)
#pragma unroll
                for (int j = 0; j < 4; j++) acc[i][j] += a[i] * b[j];
        }
        __syncthreads();
    }
#pragma unroll
    for (int i = 0; i < 4; i++) {
        size_t r = row0 + ty * 4 + i;
#pragma unroll
        for (int j = 0; j < 4; j++) {
            size_t c = col0 + tx * 4 + j;
            float v = acc[i][j];
            if (res) v += res[r * N + c];
            C[r * N + c] = v;
        }
    }
}

// ---------------- SGEMM with transposed B: C[M,N] = A[M,K] @ B[N,K]^T ----------------
__global__ void sgemm_nt(const float* __restrict__ A, const float* __restrict__ B,
                         float* __restrict__ C, int M, int N, int K) {
    __shared__ float As[16][64];
    __shared__ float Bs[16][64];
    int row0 = blockIdx.y * 64, col0 = blockIdx.x * 64;
    int tx = threadIdx.x, ty = threadIdx.y;
    int tid = ty * 16 + tx;
    int am = tid >> 2, ak = (tid & 3) * 4;   // also reused for B (row-major [N,K])
    float acc[4][4] = {};
    for (int k0 = 0; k0 < K; k0 += 16) {
        float4 a4 = *(const float4*)(A + (size_t)(row0 + am) * K + k0 + ak);
        As[ak + 0][am] = a4.x; As[ak + 1][am] = a4.y;
        As[ak + 2][am] = a4.z; As[ak + 3][am] = a4.w;
        float4 b4 = *(const float4*)(B + (size_t)(col0 + am) * K + k0 + ak);
        Bs[ak + 0][am] = b4.x; Bs[ak + 1][am] = b4.y;
        Bs[ak + 2][am] = b4.z; Bs[ak + 3][am] = b4.w;
        __syncthreads();
#pragma unroll
        for (int kk = 0; kk < 16; kk++) {
            float a[4], b[4];
            *(float4*)a = *(float4*)&As[kk][ty * 4];
            *(float4*)b = *(float4*)&Bs[kk][tx * 4];
#pragma unroll
            for (int i = 0; i < 4; i++)
#pragma unroll
                for (int j = 0; j < 4; j++) acc[i][j] += a[i] * b[j];
        }
        __syncthreads();
    }
#pragma unroll
    for (int i = 0; i < 4; i++) {
        size_t r = row0 + ty * 4 + i;
#pragma unroll
        for (int j = 0; j < 4; j++) {
            size_t c = col0 + tx * 4 + j;
            C[r * N + c] = acc[i][j];
        }
    }
}

// ---------------- rope (in-place on q or k) ----------------
__global__ void rope_kernel(float* x) {
    int idx = blockIdx.x * 256 + threadIdx.x;
    if (idx >= Tt * NHh * 32) return;
    int d = idx & 31;
    int h = (idx >> 5) & 15;
    int t = idx >> 9;
    int s = t & (Ss - 1);
    double inv = pow(10000.0, -(double)d / 32.0);
    double ang = (double)s * inv;
    float c = (float)cos(ang), sn = (float)sin(ang);
    float* p = x + (size_t)t * Dm + h * HDd + d;
    float x1 = p[0], x2 = p[32];
    p[0]  = x1 * c  - x2 * sn;
    p[32] = x1 * sn + x2 * c;
}

// ---------------- flash attention (fp32, causal, 64x64 tiles) ----------------
__global__ void flash_attn_kernel(const float* __restrict__ Q,
                                  const float* __restrict__ Km,
                                  const float* __restrict__ Vm,
                                  float* __restrict__ O) {
    extern __shared__ float sm[];
    float* Qs    = sm;                 // 64*65
    float* Ks    = Qs + 64 * 65;       // 64*65
    float* Vs    = Ks + 64 * 65;       // 64*64
    float* Ps    = Vs + 64 * 64;       // 64*65
    float* row_m = Ps + 64 * 65;       // 64
    float* row_l = row_m + 64;         // 64
    float* resc  = row_l + 64;         // 64

    int qt = blockIdx.x;               // q tile 0..15
    int bh = blockIdx.y;               // 0..31
    int b = bh >> 4, h = bh & 15;
    int tx = threadIdx.x, ty = threadIdx.y;
    int tid = ty * 16 + tx;

    size_t base = (size_t)b * Ss * Dm + (size_t)h * HDd;

    // load Q tile
    {
        int r = tid >> 2;
        int c4 = (tid & 3) * 16;
        const float* src = Q + base + (size_t)(qt * 64 + r) * Dm + c4;
#pragma unroll
        for (int i = 0; i < 4; i++) {
            float4 vq = *(const float4*)(src + i * 4);
            Qs[r * 65 + c4 + i * 4 + 0] = vq.x;
            Qs[r * 65 + c4 + i * 4 + 1] = vq.y;
            Qs[r * 65 + c4 + i * 4 + 2] = vq.z;
            Qs[r * 65 + c4 + i * 4 + 3] = vq.w;
        }
    }
    if (tid < 64) { row_m[tid] = -1e30f; row_l[tid] = 0.f; }

    float acc[4][4] = {};
    __syncthreads();

    for (int jt = 0; jt <= qt; jt++) {
        // load K and V tiles
        {
            int r = tid >> 2;
            int c4 = (tid & 3) * 16;
            const float* ksrc = Km + base + (size_t)(jt * 64 + r) * Dm + c4;
            const float* vsrc = Vm + base + (size_t)(jt * 64 + r) * Dm + c4;
#pragma unroll
            for (int i = 0; i < 4; i++) {
                float4 vk = *(const float4*)(ksrc + i * 4);
                Ks[r * 65 + c4 + i * 4 + 0] = vk.x;
                Ks[r * 65 + c4 + i * 4 + 1] = vk.y;
                Ks[r * 65 + c4 + i * 4 + 2] = vk.z;
                Ks[r * 65 + c4 + i * 4 + 3] = vk.w;
                float4 vv = *(const float4*)(vsrc + i * 4);
                *(float4*)&Vs[r * 64 + c4 + i * 4] = vv;
            }
        }
        __syncthreads();

        // P = Q K^T * 0.125 (+causal mask on diagonal tile)
        float p[4][4] = {};
#pragma unroll 4
        for (int d = 0; d < 64; d++) {
            float a[4], bv[4];
#pragma unroll
            for (int i = 0; i < 4; i++) a[i]  = Qs[(ty * 4 + i) * 65 + d];
#pragma unroll
            for (int j = 0; j < 4; j++) bv[j] = Ks[(tx * 4 + j) * 65 + d];
#pragma unroll
            for (int i = 0; i < 4; i++)
#pragma unroll
                for (int j = 0; j < 4; j++) p[i][j] += a[i] * bv[j];
        }
#pragma unroll
        for (int i = 0; i < 4; i++) {
            int gq = qt * 64 + ty * 4 + i;
#pragma unroll
            for (int j = 0; j < 4; j++) {
                int gk = jt * 64 + tx * 4 + j;
                float pv = p[i][j] * 0.125f;
                if (jt == qt && gk > gq) pv = -1e30f;
                Ps[(ty * 4 + i) * 65 + tx * 4 + j] = pv;
            }
        }
        __syncthreads();

        // online softmax row pass
        if (tid < 64) {
            int r = tid;
            float mx = row_m[r];
            float tmax = -1e30f;
            for (int c = 0; c < 64; c++) tmax = fmaxf(tmax, Ps[r * 65 + c]);
            float nm = fmaxf(mx, tmax);
            float sum = 0.f;
            for (int c = 0; c < 64; c++) {
                float e = expf(Ps[r * 65 + c] - nm);
                Ps[r * 65 + c] = e;
                sum += e;
            }
            float rf = expf(mx - nm);
            row_l[r] = row_l[r] * rf + sum;
            row_m[r] = nm;
            resc[r] = rf;
        }
        __syncthreads();

        // O = O*rescale + P @ V
        float rs[4];
#pragma unroll
        for (int i = 0; i < 4; i++) rs[i] = resc[ty * 4 + i];
#pragma unroll
        for (int i = 0; i < 4; i++)
#pragma unroll
            for (int j = 0; j < 4; j++) acc[i][j] *= rs[i];
#pragma unroll 4
        for (int c = 0; c < 64; c++) {
            float pv[4], vv[4];
#pragma unroll
            for (int i = 0; i < 4; i++) pv[i] = Ps[(ty * 4 + i) * 65 + c];
#pragma unroll
            for (int j = 0; j < 4; j++) vv[j] = Vs[c * 64 + tx * 4 + j];
#pragma unroll
            for (int i = 0; i < 4; i++)
#pragma unroll
                for (int j = 0; j < 4; j++) acc[i][j] += pv[i] * vv[j];
        }
        __syncthreads();
    }

    float inv_l[4];
#pragma unroll
    for (int i = 0; i < 4; i++) inv_l[i] = 1.0f / row_l[ty * 4 + i];
#pragma unroll
    for (int i = 0; i < 4; i++) {
        size_t r = qt * 64 + ty * 4 + i;
#pragma unroll
        for (int j = 0; j < 4; j++)
            O[base + r * Dm + tx * 4 + j] = acc[i][j] * inv_l[i];
    }
}

// ---------------- router: top-2 + softmax gates + expert lists ----------------
__global__ void zero_cnt_kernel(int* cnt) {
    if (threadIdx.x < Ee) cnt[threadIdx.x] = 0;
}

__global__ void router_kernel(const float* __restrict__ xn,
                              const float* __restrict__ rw,
                              int* cnt, int* toks, float* wgts) {
    int t = blockIdx.x;
    int lane = threadIdx.x;          // 64 threads
    int e = lane >> 3, sub = lane & 7;
    const float* xr = xn + (size_t)t * Dm;
    const float* wr = rw + (size_t)e * Dm;
    float s = 0.f;
    for (int i = sub; i < Dm; i += 8) s += xr[i] * wr[i];
    for (int off = 4; off > 0; off >>= 1) s += __shfl_down_sync(0xffffffffu, s, off, 8);
    __shared__ float lg[Ee];
    if (sub == 0) lg[e] = s;
    __syncthreads();
    if (threadIdx.x == 0) {
        int i0 = 0; float v0 = lg[0];
        for (int k = 1; k < Ee; k++) if (lg[k] > v0) { v0 = lg[k]; i0 = k; }
        int i1 = -1; float v1 = -1e30f;
        for (int k = 0; k < Ee; k++) {
            if (k == i0) continue;
            if (lg[k] > v1) { v1 = lg[k]; i1 = k; }
        }
        float e1 = expf(v1 - v0);
        float sum = 1.0f + e1;
        float w0 = 1.0f / sum, w1 = e1 / sum;
        int p0 = atomicAdd(&cnt[i0], 1);
        toks[i0 * Tt + p0] = t; wgts[i0 * Tt + p0] = w0;
        int p1 = atomicAdd(&cnt[i1], 1);
        toks[i1 * Tt + p1] = t; wgts[i1 * Tt + p1] = w1;
    }
}

// ---------------- MoE up: G = silu(Xg@W1) * (Xg@W3), gathered rows ----------------
__global__ void moe_up_kernel(const float* __restrict__ X, const int* __restrict__ toks,
                              const int* __restrict__ cntp,
                              const float* __restrict__ W1, const float* __restrict__ W3,
                              float* __restrict__ G) {
    int Me = *cntp;
    int row0 = blockIdx.y * 64;
    if (row0 >= Me) return;
    int col0 = blockIdx.x * 64;
    __shared__ float As[16][64];
    __shared__ float B1s[16][64];
    __shared__ float B3s[16][64];
    int tx = threadIdx.x, ty = threadIdx.y;
    int tid = ty * 16 + tx;
    int am = tid >> 2, ak = (tid & 3) * 4;
    int bk = tid >> 4, bn = (tid & 15) * 4;
    int m = row0 + am;
    int tsrc = toks[m < Me ? m : (Me - 1)];
    float acc1[4][4] = {}, acc3[4][4] = {};
    for (int k0 = 0; k0 < Dm; k0 += 16) {
        float4 a4 = *(const float4*)(X + (size_t)tsrc * Dm + k0 + ak);
        As[ak + 0][am] = a4.x; As[ak + 1][am] = a4.y;
        As[ak + 2][am] = a4.z; As[ak + 3][am] = a4.w;
        *(float4*)&B1s[bk][bn] = *(const float4*)(W1 + (size_t)(k0 + bk) * HIDh + col0 + bn);
        *(float4*)&B3s[bk][bn] = *(const float4*)(W3 + (size_t)(k0 + bk) * HIDh + col0 + bn);
        __syncthreads();
#pragma unroll
        for (int kk = 0; kk < 16; kk++) {
            float a[4], b1[4], b3[4];
            *(float4*)a  = *(float4*)&As[kk][ty * 4];
            *(float4*)b1 = *(float4*)&B1s[kk][tx * 4];
            *(float4*)b3 = *(float4*)&B3s[kk][tx * 4];
#pragma unroll
            for (int i = 0; i < 4; i++)
#pragma unroll
                for (int j = 0; j < 4; j++) {
                    acc1[i][j] += a[i] * b1[j];
                    acc3[i][j] += a[i] * b3[j];
                }
        }
        __syncthreads();
    }
#pragma unroll
    for (int i = 0; i < 4; i++) {
        int r = row0 + ty * 4 + i;
        if (r < Me) {
#pragma unroll
            for (int j = 0; j < 4; j++) {
                int c = col0 + tx * 4 + j;
                float h1 = acc1[i][j];
                float sil = h1 / (1.0f + expf(-h1));
                G[(size_t)r * HIDh + c] = sil * acc3[i][j];
            }
        }
    }
}

// ---------------- MoE down: X[tok[i]] += wgt[i] * (G @ W2) ----------------
__global__ void moe_down_kernel(const float* __restrict__ G, const float* __restrict__ W2,
                                const int* __restrict__ toks, const float* __restrict__ wgt,
                                const int* __restrict__ cntp, float* X) {
    int Me = *cntp;
    int row0 = blockIdx.y * 64;
    if (row0 >= Me) return;
    int col0 = blockIdx.x * 64;
    __shared__ float As[16][64];
    __shared__ float Bs[16][64];
    int tx = threadIdx.x, ty = threadIdx.y;
    int tid = ty * 16 + tx;
    int am = tid >> 2, ak = (tid & 3) * 4;
    int bk = tid >> 4, bn = (tid & 15) * 4;
    int m = row0 + am;
    int mr = m < Me ? m : (Me - 1);
    float acc[4][4] = {};
    for (int k0 = 0; k0 < HIDh; k0 += 16) {
        float4 a4 = *(const float4*)(G + (size_t)mr * HIDh + k0 + ak);
        As[ak + 0][am] = a4.x; As[ak + 1][am] = a4.y;
        As[ak + 2][am] = a4.z; As[ak + 3][am] = a4.w;
        *(float4*)&Bs[bk][bn] = *(const float4*)(W2 + (size_t)(k0 + bk) * Dm + col0 + bn);
        __syncthreads();
#pragma unroll
        for (int kk = 0; kk < 16; kk++) {
            float a[4], b[4];
            *(float4*)a = *(float4*)&As[kk][ty * 4];
            *(float4*)b = *(float4*)&Bs[kk][tx * 4];
#pragma unroll
            for (int i = 0; i < 4; i++)
#pragma unroll
                for (int j = 0; j < 4; j++) acc[i][j] += a[i] * b[j];
        }
        __syncthreads();
    }
#pragma unroll
    for (int i = 0; i < 4; i++) {
        int r = row0 + ty * 4 + i;
        if (r < Me) {
            int t = toks[r];
            float w = wgt[r];
#pragma unroll
            for (int j = 0; j < 4; j++) {
                int c = col0 + tx * 4 + j;
                X[(size_t)t * Dm + c] += w * acc[i][j];
            }
        }
    }
}

// ---------------- launcher ----------------
extern "C" void kernel_launch(void* const* d_in, const int* in_sizes, int n_in,
                              void* d_out, int out_size) {
    (void)in_sizes; (void)n_in; (void)out_size;
    const int*   tokens       = (const int*)d_in[0];
    const float* embed        = (const float*)d_in[1];
    const float* attn_norm_w  = (const float*)d_in[2];
    const float* wq           = (const float*)d_in[3];
    const float* wk           = (const float*)d_in[4];
    const float* wv           = (const float*)d_in[5];
    const float* wo           = (const float*)d_in[6];
    const float* moe_norm_w   = (const float*)d_in[7];
    const float* router_w     = (const float*)d_in[8];
    const float* w1           = (const float*)d_in[9];
    const float* w2           = (const float*)d_in[10];
    const float* w3           = (const float*)d_in[11];
    const float* final_norm_w = (const float*)d_in[12];
    float* out = (float*)d_out;

    float *x, *xn, *q, *k, *v, *ctx, *gbuf, *wgts;
    int *cnt, *toks;
    cudaGetSymbolAddress((void**)&x,    g_x);
    cudaGetSymbolAddress((void**)&xn,   g_xn);
    cudaGetSymbolAddress((void**)&q,    g_q);
    cudaGetSymbolAddress((void**)&k,    g_k);
    cudaGetSymbolAddress((void**)&v,    g_v);
    cudaGetSymbolAddress((void**)&ctx,  g_ctx);
    cudaGetSymbolAddress((void**)&gbuf, g_gbuf);
    cudaGetSymbolAddress((void**)&cnt,  g_cnt);
    cudaGetSymbolAddress((void**)&toks, g_toks);
    cudaGetSymbolAddress((void**)&wgts, g_wgts);

    const int FLASH_SMEM = (3 * 64 * 65 + 64 * 64 + 3 * 64) * 4;
    cudaFuncSetAttribute(flash_attn_kernel,
                         cudaFuncAttributeMaxDynamicSharedMemorySize, FLASH_SMEM);

    dim3 b1(16, 16);

    embed_kernel<<<Tt, 256>>>(tokens, embed, x);

    for (int l = 0; l < Ll; l++) {
        rmsnorm_kernel<<<Tt, 256>>>(x, attn_norm_w + (size_t)l * Dm, xn);

        dim3 g1(Dm / 64, Tt / 64);
        sgemm_nn<<<g1, b1>>>(xn, wq + (size_t)l * Dm * Dm, q, nullptr, Tt, Dm, Dm);
        sgemm_nn<<<g1, b1>>>(xn, wk + (size_t)l * Dm * Dm, k, nullptr, Tt, Dm, Dm);
        sgemm_nn<<<g1, b1>>>(xn, wv + (size_t)l * Dm * Dm, v, nullptr, Tt, Dm, Dm);

        int nrope = Tt * NHh * 32;
        rope_kernel<<<(nrope + 255) / 256, 256>>>(q);
        rope_kernel<<<(nrope + 255) / 256, 256>>>(k);

        flash_attn_kernel<<<dim3(Ss / 64, 2 * NHh), b1, FLASH_SMEM>>>(q, k, v, ctx);

        // x = x + ctx @ wo
        sgemm_nn<<<g1, b1>>>(ctx, wo + (size_t)l * Dm * Dm, x, x, Tt, Dm, Dm);

        rmsnorm_kernel<<<Tt, 256>>>(x, moe_norm_w + (size_t)l * Dm, xn);

        zero_cnt_kernel<<<1, 32>>>(cnt);
        router_kernel<<<Tt, 64>>>(xn, router_w + (size_t)l * Ee * Dm, cnt, toks, wgts);

        for (int e = 0; e < Ee; e++) {
            moe_up_kernel<<<dim3(HIDh / 64, Tt / 64), b1>>>(
                xn, toks + e * Tt, cnt + e,
                w1 + ((size_t)l * Ee + e) * Dm * HIDh,
                w3 + ((size_t)l * Ee + e) * Dm * HIDh, gbuf);
            moe_down_kernel<<<dim3(Dm / 64, Tt / 64), b1>>>(
                gbuf, w2 + ((size_t)l * Ee + e) * HIDh * Dm,
                toks + e * Tt, wgts + e * Tt, cnt + e, x);
        }
    }

    rmsnorm_kernel<<<Tt, 256>>>(x, final_norm_w, xn);
    sgemm_nt<<<dim3(Vv / 64, Tt / 64), b1>>>(xn, embed, out, Tt, Vv, Dm);
}

// round 6
// speedup vs baseline: 2.8885x; 2.8885x over previous
#include <cuda_runtime.h>
#include <cuda_bf16.h>
#include <math.h>
#include <stdint.h>

#define Tt   2048
#define Dm   1024
#define NHh  16
#define HDd  64
#define Ll   2
#define HIDh 2048
#define Ee   8
#define Ss   1024
#define Vv   32000

// ---------------- scratch ----------------
__device__ float g_x[Tt * Dm];
__device__ float g_xn[Tt * Dm];
__device__ float g_q[Tt * Dm];
__device__ float g_k[Tt * Dm];
__device__ float g_v[Tt * Dm];
__device__ float g_ctx[Tt * Dm];
__device__ float g_gbuf[(size_t)2 * Tt * HIDh];   // packed rows: sum(cnt_e) == 2*Tt
__device__ int   g_cnt[Ee];
__device__ int   g_off[Ee + 1];
__device__ int   g_toks[Ee * Tt];
__device__ float g_wgts[Ee * Tt];

// ---------------- helpers ----------------
__device__ __forceinline__ uint32_t cvta_smem(const void* p) {
    uint32_t a;
    asm("{ .reg .u64 t; cvta.to.shared.u64 t, %1; cvt.u32.u64 %0, t; }" : "=r"(a) : "l"(p));
    return a;
}
__device__ __forceinline__ void ldsm_x4(uint32_t addr, uint32_t& r0, uint32_t& r1,
                                        uint32_t& r2, uint32_t& r3) {
    asm volatile("ldmatrix.sync.aligned.m8n8.x4.shared.b16 {%0,%1,%2,%3}, [%4];"
                 : "=r"(r0), "=r"(r1), "=r"(r2), "=r"(r3) : "r"(addr));
}
__device__ __forceinline__ void mma_bf16(float* c, const uint32_t* a, const uint32_t* b) {
    asm volatile("mma.sync.aligned.m16n8k16.row.col.f32.bf16.bf16.f32 "
                 "{%0,%1,%2,%3}, {%4,%5,%6,%7}, {%8,%9}, {%0,%1,%2,%3};"
                 : "+f"(c[0]), "+f"(c[1]), "+f"(c[2]), "+f"(c[3])
                 : "r"(a[0]), "r"(a[1]), "r"(a[2]), "r"(a[3]), "r"(b[0]), "r"(b[1]));
}
__device__ __forceinline__ uint32_t sw128(uint32_t byte) {
    return byte ^ ((byte >> 3) & 0x70);
}
// split float4 -> 4 bf16 hi (uint2) + 4 bf16 lo (uint2)
__device__ __forceinline__ void split4(float4 v, uint2& hi, uint2& lo) {
    __nv_bfloat162 h01 = __floats2bfloat162_rn(v.x, v.y);
    __nv_bfloat162 h23 = __floats2bfloat162_rn(v.z, v.w);
    float2 f01 = __bfloat1622float2(h01);
    float2 f23 = __bfloat1622float2(h23);
    __nv_bfloat162 l01 = __floats2bfloat162_rn(v.x - f01.x, v.y - f01.y);
    __nv_bfloat162 l23 = __floats2bfloat162_rn(v.z - f23.x, v.w - f23.y);
    hi.x = *(uint32_t*)&h01; hi.y = *(uint32_t*)&h23;
    lo.x = *(uint32_t*)&l01; lo.y = *(uint32_t*)&l23;
}

// ================= bf16x3 split-precision mma.sync GEMM =================
// Tile: BM=128, BN=128, BK=32. 256 threads = 8 warps (4 M x 2 N), warp tile 32x64.
// smem row (128B): bytes 0..63 = hi[32 k] bf16, bytes 64..127 = lo[32 k] bf16, SW128.
// GATHER: A rows via token list. BT: B is [N,K] row-major (else [K,N] transposed on load).
// EPI: 0=store(+RES), 1=silu store, 2=multiply-existing, 3=scatter atomicAdd(w*v)
template<bool GATHER, bool BT, int EPI, bool RES>
__global__ void __launch_bounds__(256) mma_gemm(
    const float* __restrict__ A,
    const float* __restrict__ Bw,
    float* __restrict__ C,
    const int* __restrict__ toksAll,
    const float* __restrict__ wgtsAll,
    const int* __restrict__ cntAll,
    const int* __restrict__ offsAll,
    int Ndim, int Kdim, long long bStride)
{
    extern __shared__ char dyn_raw[];
    __shared__ int   s_tok[128];
    __shared__ float s_wgt[128];

    constexpr bool EXPERT = (EPI >= 1);
    int e = EXPERT ? blockIdx.z : 0;
    int Me = EXPERT ? cntAll[e] : (1 << 30);
    int row0 = blockIdx.y * 128;
    if (row0 >= Me) return;
    int col0 = blockIdx.x * 128;

    int eoff = EXPERT ? offsAll[e] : 0;
    const float* Az = (EPI == 3) ? A + (size_t)eoff * Kdim : A;
    float* Cz = (EPI == 1 || EPI == 2) ? C + (size_t)eoff * Ndim : C;
    const float* Bz = Bw + (EXPERT ? (long long)e * bStride : 0);

    int tid = threadIdx.x;
    int wid = tid >> 5, lane = tid & 31;
    int warp_m = wid & 3, warp_n = wid >> 2;

    uint32_t rawaddr = cvta_smem(dyn_raw);
    uint32_t sbase = (rawaddr + 1023u) & ~1023u;
    char* smg = dyn_raw + (sbase - rawaddr);
    // A stages at 0, 16384; B stages at 32768, 49152

    if (EXPERT && tid < 128) {
        int m = row0 + tid;
        int mc = m < Me ? m : (Me - 1);
        s_tok[tid] = toksAll[e * Tt + mc];
        s_wgt[tid] = wgtsAll[e * Tt + mc];
    }
    if (EXPERT) __syncthreads();

    const int NK = Kdim / 32;

    float4 ar[4];
    float4 brv[4];
    float  brt[16];

    auto LDG_A = [&](int kc) {
        int k0 = kc * 32;
#pragma unroll
        for (int i = 0; i < 4; i++) {
            int idx = tid + 256 * i;
            int r = idx >> 3, f = idx & 7;
            long row;
            if (GATHER)          row = (long)s_tok[r];
            else if (EPI == 3) { int rr = row0 + r; row = (long)(rr < Me ? rr : (Me - 1)); }
            else                 row = (long)(row0 + r);
            ar[i] = *(const float4*)(Az + row * (long)Kdim + k0 + f * 4);
        }
    };
    auto STS_A = [&](int stage) {
        uint32_t base = stage * 16384;
#pragma unroll
        for (int i = 0; i < 4; i++) {
            int idx = tid + 256 * i;
            int r = idx >> 3, f = idx & 7;
            uint2 hi, lo;
            split4(ar[i], hi, lo);
            *(uint2*)(smg + sw128(base + r * 128 + f * 8)) = hi;
            *(uint2*)(smg + sw128(base + r * 128 + 64 + f * 8)) = lo;
        }
    };
    auto LDG_B = [&](int kc) {
        int k0 = kc * 32;
        if (BT) {
#pragma unroll
            for (int i = 0; i < 4; i++) {
                int idx = tid + 256 * i;
                int r = idx >> 3, f = idx & 7;
                brv[i] = *(const float4*)(Bz + (long)(col0 + r) * Kdim + k0 + f * 4);
            }
        } else {
            int n = tid & 127, kh = (tid >> 7) * 16;
            const float* p = Bz + (long)(k0 + kh) * Ndim + col0 + n;
#pragma unroll
            for (int q = 0; q < 16; q++) brt[q] = p[(long)q * Ndim];
        }
    };
    auto STS_B = [&](int stage) {
        uint32_t base = 32768 + stage * 16384;
        if (BT) {
#pragma unroll
            for (int i = 0; i < 4; i++) {
                int idx = tid + 256 * i;
                int r = idx >> 3, f = idx & 7;
                uint2 hi, lo;
                split4(brv[i], hi, lo);
                *(uint2*)(smg + sw128(base + r * 128 + f * 8)) = hi;
                *(uint2*)(smg + sw128(base + r * 128 + 64 + f * 8)) = lo;
            }
        } else {
            int n = tid & 127, kh = (tid >> 7) * 16;
#pragma unroll
            for (int q4 = 0; q4 < 4; q4++) {
                float4 v = make_float4(brt[q4 * 4 + 0], brt[q4 * 4 + 1],
                                       brt[q4 * 4 + 2], brt[q4 * 4 + 3]);
                uint2 hi, lo;
                split4(v, hi, lo);
                uint32_t cb = (kh + q4 * 4) * 2;
                *(uint2*)(smg + sw128(base + n * 128 + cb)) = hi;
                *(uint2*)(smg + sw128(base + n * 128 + 64 + cb)) = lo;
            }
        }
    };

    float c[2][8][4];
#pragma unroll
    for (int mt = 0; mt < 2; mt++)
#pragma unroll
        for (int nt = 0; nt < 8; nt++)
#pragma unroll
            for (int q = 0; q < 4; q++) c[mt][nt][q] = 0.f;

    LDG_A(0); LDG_B(0);
    STS_A(0); STS_B(0);
    if (NK > 1) { LDG_A(1); LDG_B(1); }
    __syncthreads();

    // ldmatrix geometry: 16-byte chunk = 8 bf16 along k
    int a_row = warp_m * 32 + (lane & 15);
    int a_cb  = (lane & 16) ? 16 : 0;
    int b_row = warp_n * 64 + (lane & 7) + ((lane & 16) ? 8 : 0);
    int b_cb  = (lane & 8) ? 16 : 0;

    for (int kc = 0; kc < NK; kc++) {
        int cur = kc & 1;
        if (kc + 1 < NK) { STS_A(cur ^ 1); STS_B(cur ^ 1); }
        if (kc + 2 < NK) { LDG_A(kc + 2); LDG_B(kc + 2); }

        uint32_t stA = cur * 16384;
        uint32_t stB = 32768 + cur * 16384;
#pragma unroll
        for (int ks = 0; ks < 2; ks++) {
            int kb = ks * 32;                       // 16 bf16 = 32 bytes per k-step
            uint32_t ah[2][4], al[2][4];
#pragma unroll
            for (int mt = 0; mt < 2; mt++) {
                uint32_t rb = stA + (a_row + mt * 16) * 128 + kb + a_cb;
                ldsm_x4(sbase + sw128(rb),      ah[mt][0], ah[mt][1], ah[mt][2], ah[mt][3]);
                ldsm_x4(sbase + sw128(rb + 64), al[mt][0], al[mt][1], al[mt][2], al[mt][3]);
            }
            uint32_t bh[8][2], bl[8][2];
#pragma unroll
            for (int ntp = 0; ntp < 4; ntp++) {
                uint32_t rb = stB + (b_row + ntp * 16) * 128 + kb + b_cb;
                ldsm_x4(sbase + sw128(rb),      bh[2 * ntp][0], bh[2 * ntp][1],
                        bh[2 * ntp + 1][0], bh[2 * ntp + 1][1]);
                ldsm_x4(sbase + sw128(rb + 64), bl[2 * ntp][0], bl[2 * ntp][1],
                        bl[2 * ntp + 1][0], bl[2 * ntp + 1][1]);
            }
#pragma unroll
            for (int mt = 0; mt < 2; mt++)
#pragma unroll
                for (int nt = 0; nt < 8; nt++) {
                    mma_bf16(c[mt][nt], ah[mt], bh[nt]);
                    mma_bf16(c[mt][nt], ah[mt], bl[nt]);
                    mma_bf16(c[mt][nt], al[mt], bh[nt]);
                }
        }
        __syncthreads();
    }

    // ---- epilogue ----
    int lr = lane >> 2, lc = (lane & 3) * 2;
#pragma unroll
    for (int mt = 0; mt < 2; mt++) {
#pragma unroll
        for (int half = 0; half < 2; half++) {
            int lrow = warp_m * 32 + mt * 16 + half * 8 + lr;
            int grow = row0 + lrow;
            bool ok = EXPERT ? (grow < Me) : true;
            if (!ok) continue;
#pragma unroll
            for (int nt = 0; nt < 8; nt++) {
                int gcol = col0 + warp_n * 64 + nt * 8 + lc;
                float v0 = c[mt][nt][half * 2 + 0];
                float v1 = c[mt][nt][half * 2 + 1];
                if (EPI == 0) {
                    size_t idx = (size_t)grow * Ndim + gcol;
                    if (RES) { Cz[idx] += v0; Cz[idx + 1] += v1; }
                    else {
                        float2 st = make_float2(v0, v1);
                        *(float2*)(Cz + idx) = st;
                    }
                } else if (EPI == 1) {
                    size_t idx = (size_t)grow * Ndim + gcol;
                    float2 st = make_float2(v0 / (1.0f + expf(-v0)),
                                            v1 / (1.0f + expf(-v1)));
                    *(float2*)(Cz + idx) = st;
                } else if (EPI == 2) {
                    size_t idx = (size_t)grow * Ndim + gcol;
                    float2 old = *(float2*)(Cz + idx);
                    float2 st = make_float2(old.x * v0, old.y * v1);
                    *(float2*)(Cz + idx) = st;
                } else {  // EPI == 3
                    float w = s_wgt[lrow];
                    float* dst = Cz + (size_t)s_tok[lrow] * Ndim + gcol;
                    atomicAdd(dst,     w * v0);
                    atomicAdd(dst + 1, w * v1);
                }
            }
        }
    }
}

// ---------------- small kernels ----------------
__global__ void embed_kernel(const int* __restrict__ tokens,
                             const float* __restrict__ embed,
                             float* __restrict__ x) {
    int t = blockIdx.x;
    int tok = tokens[t];
    const float4* src = (const float4*)(embed + (size_t)tok * Dm);
    float4* dst = (float4*)(x + (size_t)t * Dm);
    for (int i = threadIdx.x; i < Dm / 4; i += blockDim.x) dst[i] = src[i];
}

__global__ void rmsnorm_kernel(const float* __restrict__ x,
                               const float* __restrict__ w,
                               float* __restrict__ y) {
    int t = blockIdx.x;
    const float* xr = x + (size_t)t * Dm;
    float s = 0.f;
    for (int i = threadIdx.x; i < Dm; i += 256) { float v = xr[i]; s += v * v; }
    __shared__ float red[256];
    red[threadIdx.x] = s;
    __syncthreads();
    for (int off = 128; off > 0; off >>= 1) {
        if (threadIdx.x < off) red[threadIdx.x] += red[threadIdx.x + off];
        __syncthreads();
    }
    float scale = rsqrtf(red[0] / (float)Dm + 1e-6f);
    for (int i = threadIdx.x; i < Dm; i += 256)
        y[(size_t)t * Dm + i] = xr[i] * scale * w[i];
}

__global__ void rope_kernel(float* x) {
    int idx = blockIdx.x * 256 + threadIdx.x;
    if (idx >= Tt * NHh * 32) return;
    int d = idx & 31;
    int h = (idx >> 5) & 15;
    int t = idx >> 9;
    int s = t & (Ss - 1);
    double inv = pow(10000.0, -(double)d / 32.0);
    double ang = (double)s * inv;
    float c = (float)cos(ang), sn = (float)sin(ang);
    float* p = x + (size_t)t * Dm + h * HDd + d;
    float x1 = p[0], x2 = p[32];
    p[0]  = x1 * c  - x2 * sn;
    p[32] = x1 * sn + x2 * c;
}

// ---------------- flash attention (fp32, causal, 64x64 tiles) ----------------
__global__ void flash_attn_kernel(const float* __restrict__ Q,
                                  const float* __restrict__ Km,
                                  const float* __restrict__ Vm,
                                  float* __restrict__ O) {
    extern __shared__ float sm[];
    float* Qs    = sm;
    float* Ks    = Qs + 64 * 65;
    float* Vs    = Ks + 64 * 65;
    float* Ps    = Vs + 64 * 64;
    float* row_m = Ps + 64 * 65;
    float* row_l = row_m + 64;
    float* resc  = row_l + 64;

    int qt = blockIdx.x;
    int bh = blockIdx.y;
    int b = bh >> 4, h = bh & 15;
    int tx = threadIdx.x, ty = threadIdx.y;
    int tid = ty * 16 + tx;

    size_t base = (size_t)b * Ss * Dm + (size_t)h * HDd;

    {
        int r = tid >> 2;
        int c4 = (tid & 3) * 16;
        const float* src = Q + base + (size_t)(qt * 64 + r) * Dm + c4;
#pragma unroll
        for (int i = 0; i < 4; i++) {
            float4 vq = *(const float4*)(src + i * 4);
            Qs[r * 65 + c4 + i * 4 + 0] = vq.x;
            Qs[r * 65 + c4 + i * 4 + 1] = vq.y;
            Qs[r * 65 + c4 + i * 4 + 2] = vq.z;
            Qs[r * 65 + c4 + i * 4 + 3] = vq.w;
        }
    }
    if (tid < 64) { row_m[tid] = -1e30f; row_l[tid] = 0.f; }

    float acc[4][4] = {};
    __syncthreads();

    for (int jt = 0; jt <= qt; jt++) {
        {
            int r = tid >> 2;
            int c4 = (tid & 3) * 16;
            const float* ksrc = Km + base + (size_t)(jt * 64 + r) * Dm + c4;
            const float* vsrc = Vm + base + (size_t)(jt * 64 + r) * Dm + c4;
#pragma unroll
            for (int i = 0; i < 4; i++) {
                float4 vk = *(const float4*)(ksrc + i * 4);
                Ks[r * 65 + c4 + i * 4 + 0] = vk.x;
                Ks[r * 65 + c4 + i * 4 + 1] = vk.y;
                Ks[r * 65 + c4 + i * 4 + 2] = vk.z;
                Ks[r * 65 + c4 + i * 4 + 3] = vk.w;
                float4 vv = *(const float4*)(vsrc + i * 4);
                *(float4*)&Vs[r * 64 + c4 + i * 4] = vv;
            }
        }
        __syncthreads();

        float p[4][4] = {};
#pragma unroll 4
        for (int d = 0; d < 64; d++) {
            float a[4], bv[4];
#pragma unroll
            for (int i = 0; i < 4; i++) a[i]  = Qs[(ty * 4 + i) * 65 + d];
#pragma unroll
            for (int j = 0; j < 4; j++) bv[j] = Ks[(tx * 4 + j) * 65 + d];
#pragma unroll
            for (int i = 0; i < 4; i++)
#pragma unroll
                for (int j = 0; j < 4; j++) p[i][j] += a[i] * bv[j];
        }
#pragma unroll
        for (int i = 0; i < 4; i++) {
            int gq = qt * 64 + ty * 4 + i;
#pragma unroll
            for (int j = 0; j < 4; j++) {
                int gk = jt * 64 + tx * 4 + j;
                float pv = p[i][j] * 0.125f;
                if (jt == qt && gk > gq) pv = -1e30f;
                Ps[(ty * 4 + i) * 65 + tx * 4 + j] = pv;
            }
        }
        __syncthreads();

        if (tid < 64) {
            int r = tid;
            float mx = row_m[r];
            float tmax = -1e30f;
            for (int cc = 0; cc < 64; cc++) tmax = fmaxf(tmax, Ps[r * 65 + cc]);
            float nm = fmaxf(mx, tmax);
            float sum = 0.f;
            for (int cc = 0; cc < 64; cc++) {
                float ev = expf(Ps[r * 65 + cc] - nm);
                Ps[r * 65 + cc] = ev;
                sum += ev;
            }
            float rf = expf(mx - nm);
            row_l[r] = row_l[r] * rf + sum;
            row_m[r] = nm;
            resc[r] = rf;
        }
        __syncthreads();

        float rs[4];
#pragma unroll
        for (int i = 0; i < 4; i++) rs[i] = resc[ty * 4 + i];
#pragma unroll
        for (int i = 0; i < 4; i++)
#pragma unroll
            for (int j = 0; j < 4; j++) acc[i][j] *= rs[i];
#pragma unroll 4
        for (int cc = 0; cc < 64; cc++) {
            float pv[4], vv[4];
#pragma unroll
            for (int i = 0; i < 4; i++) pv[i] = Ps[(ty * 4 + i) * 65 + cc];
#pragma unroll
            for (int j = 0; j < 4; j++) vv[j] = Vs[cc * 64 + tx * 4 + j];
#pragma unroll
            for (int i = 0; i < 4; i++)
#pragma unroll
                for (int j = 0; j < 4; j++) acc[i][j] += pv[i] * vv[j];
        }
        __syncthreads();
    }

    float inv_l[4];
#pragma unroll
    for (int i = 0; i < 4; i++) inv_l[i] = 1.0f / row_l[ty * 4 + i];
#pragma unroll
    for (int i = 0; i < 4; i++) {
        size_t r = qt * 64 + ty * 4 + i;
#pragma unroll
        for (int j = 0; j < 4; j++)
            O[base + r * Dm + tx * 4 + j] = acc[i][j] * inv_l[i];
    }
}

// ---------------- router ----------------
__global__ void zero_cnt_kernel(int* cnt) {
    if (threadIdx.x < Ee) cnt[threadIdx.x] = 0;
}

__global__ void router_kernel(const float* __restrict__ xn,
                              const float* __restrict__ rw,
                              int* cnt, int* toks, float* wgts) {
    int t = blockIdx.x;
    int lane = threadIdx.x;
    int e = lane >> 3, sub = lane & 7;
    const float* xr = xn + (size_t)t * Dm;
    const float* wr = rw + (size_t)e * Dm;
    float s = 0.f;
    for (int i = sub; i < Dm; i += 8) s += xr[i] * wr[i];
    for (int off = 4; off > 0; off >>= 1) s += __shfl_down_sync(0xffffffffu, s, off, 8);
    __shared__ float lg[Ee];
    if (sub == 0) lg[e] = s;
    __syncthreads();
    if (threadIdx.x == 0) {
        int i0 = 0; float v0 = lg[0];
        for (int k = 1; k < Ee; k++) if (lg[k] > v0) { v0 = lg[k]; i0 = k; }
        int i1 = -1; float v1 = -1e30f;
        for (int k = 0; k < Ee; k++) {
            if (k == i0) continue;
            if (lg[k] > v1) { v1 = lg[k]; i1 = k; }
        }
        float e1 = expf(v1 - v0);
        float sum = 1.0f + e1;
        float w0 = 1.0f / sum, w1 = e1 / sum;
        int p0 = atomicAdd(&cnt[i0], 1);
        toks[i0 * Tt + p0] = t; wgts[i0 * Tt + p0] = w0;
        int p1 = atomicAdd(&cnt[i1], 1);
        toks[i1 * Tt + p1] = t; wgts[i1 * Tt + p1] = w1;
    }
}

__global__ void offsets_kernel(const int* __restrict__ cnt, int* __restrict__ off) {
    if (threadIdx.x == 0) {
        int s = 0;
        for (int e = 0; e < Ee; e++) { off[e] = s; s += cnt[e]; }
        off[Ee] = s;
    }
}

// ---------------- launcher ----------------
extern "C" void kernel_launch(void* const* d_in, const int* in_sizes, int n_in,
                              void* d_out, int out_size) {
    (void)in_sizes; (void)n_in; (void)out_size;
    const int*   tokens       = (const int*)d_in[0];
    const float* embed        = (const float*)d_in[1];
    const float* attn_norm_w  = (const float*)d_in[2];
    const float* wq           = (const float*)d_in[3];
    const float* wk           = (const float*)d_in[4];
    const float* wv           = (const float*)d_in[5];
    const float* wo           = (const float*)d_in[6];
    const float* moe_norm_w   = (const float*)d_in[7];
    const float* router_w     = (const float*)d_in[8];
    const float* w1           = (const float*)d_in[9];
    const float* w2           = (const float*)d_in[10];
    const float* w3           = (const float*)d_in[11];
    const float* final_norm_w = (const float*)d_in[12];
    float* out = (float*)d_out;

    float *x, *xn, *q, *k, *v, *ctx, *gbuf, *wgts;
    int *cnt, *toks, *offs;
    cudaGetSymbolAddress((void**)&x,    g_x);
    cudaGetSymbolAddress((void**)&xn,   g_xn);
    cudaGetSymbolAddress((void**)&q,    g_q);
    cudaGetSymbolAddress((void**)&k,    g_k);
    cudaGetSymbolAddress((void**)&v,    g_v);
    cudaGetSymbolAddress((void**)&ctx,  g_ctx);
    cudaGetSymbolAddress((void**)&gbuf, g_gbuf);
    cudaGetSymbolAddress((void**)&cnt,  g_cnt);
    cudaGetSymbolAddress((void**)&offs, g_off);
    cudaGetSymbolAddress((void**)&toks, g_toks);
    cudaGetSymbolAddress((void**)&wgts, g_wgts);

    const int FLASH_SMEM = (3 * 64 * 65 + 64 * 64 + 3 * 64) * 4;
    cudaFuncSetAttribute(flash_attn_kernel,
                         cudaFuncAttributeMaxDynamicSharedMemorySize, FLASH_SMEM);

    const int GEMM_SMEM = 64 * 1024 + 1024;
    cudaFuncSetAttribute((const void*)mma_gemm<false,false,0,false>, cudaFuncAttributeMaxDynamicSharedMemorySize, GEMM_SMEM);
    cudaFuncSetAttribute((const void*)mma_gemm<false,false,0,true >, cudaFuncAttributeMaxDynamicSharedMemorySize, GEMM_SMEM);
    cudaFuncSetAttribute((const void*)mma_gemm<false,true ,0,false>, cudaFuncAttributeMaxDynamicSharedMemorySize, GEMM_SMEM);
    cudaFuncSetAttribute((const void*)mma_gemm<true ,false,1,false>, cudaFuncAttributeMaxDynamicSharedMemorySize, GEMM_SMEM);
    cudaFuncSetAttribute((const void*)mma_gemm<true ,false,2,false>, cudaFuncAttributeMaxDynamicSharedMemorySize, GEMM_SMEM);
    cudaFuncSetAttribute((const void*)mma_gemm<false,false,3,false>, cudaFuncAttributeMaxDynamicSharedMemorySize, GEMM_SMEM);

    embed_kernel<<<Tt, 256>>>(tokens, embed, x);

    long long upB = (long long)Dm * HIDh;
    long long dnB = (long long)HIDh * Dm;

    for (int l = 0; l < Ll; l++) {
        rmsnorm_kernel<<<Tt, 256>>>(x, attn_norm_w + (size_t)l * Dm, xn);

        dim3 gqkv(Dm / 128, Tt / 128, 1);
        mma_gemm<false,false,0,false><<<gqkv, 256, GEMM_SMEM>>>(
            xn, wq + (size_t)l * Dm * Dm, q, nullptr, nullptr, nullptr, nullptr, Dm, Dm, 0);
        mma_gemm<false,false,0,false><<<gqkv, 256, GEMM_SMEM>>>(
            xn, wk + (size_t)l * Dm * Dm, k, nullptr, nullptr, nullptr, nullptr, Dm, Dm, 0);
        mma_gemm<false,false,0,false><<<gqkv, 256, GEMM_SMEM>>>(
            xn, wv + (size_t)l * Dm * Dm, v, nullptr, nullptr, nullptr, nullptr, Dm, Dm, 0);

        int nrope = Tt * NHh * 32;
        rope_kernel<<<(nrope + 255) / 256, 256>>>(q);
        rope_kernel<<<(nrope + 255) / 256, 256>>>(k);

        flash_attn_kernel<<<dim3(Ss / 64, 2 * NHh), dim3(16, 16), FLASH_SMEM>>>(q, k, v, ctx);

        // x += ctx @ wo
        mma_gemm<false,false,0,true><<<gqkv, 256, GEMM_SMEM>>>(
            ctx, wo + (size_t)l * Dm * Dm, x, nullptr, nullptr, nullptr, nullptr, Dm, Dm, 0);

        rmsnorm_kernel<<<Tt, 256>>>(x, moe_norm_w + (size_t)l * Dm, xn);

        zero_cnt_kernel<<<1, 32>>>(cnt);
        router_kernel<<<Tt, 64>>>(xn, router_w + (size_t)l * Ee * Dm, cnt, toks, wgts);
        offsets_kernel<<<1, 32>>>(cnt, offs);

        // MoE pass1: gbuf = silu(Xg @ W1)
        mma_gemm<true,false,1,false><<<dim3(HIDh / 128, Tt / 128, Ee), 256, GEMM_SMEM>>>(
            xn, w1 + (size_t)l * Ee * upB, gbuf, toks, wgts, cnt, offs, HIDh, Dm, upB);
        // MoE pass2: gbuf *= (Xg @ W3)
        mma_gemm<true,false,2,false><<<dim3(HIDh / 128, Tt / 128, Ee), 256, GEMM_SMEM>>>(
            xn, w3 + (size_t)l * Ee * upB, gbuf, toks, wgts, cnt, offs, HIDh, Dm, upB);
        // MoE down: x[tok] += w * (gbuf @ W2)
        mma_gemm<false,false,3,false><<<dim3(Dm / 128, Tt / 128, Ee), 256, GEMM_SMEM>>>(
            gbuf, w2 + (size_t)l * Ee * dnB, x, toks, wgts, cnt, offs, Dm, HIDh, dnB);
    }

    rmsnorm_kernel<<<Tt, 256>>>(x, final_norm_w, xn);
    mma_gemm<false,true,0,false><<<dim3(Vv / 128, Tt / 128, 1), 256, GEMM_SMEM>>>(
        xn, embed, out, nullptr, nullptr, nullptr, nullptr, Vv, Dm, 0);
}